// round 2
// baseline (speedup 1.0000x reference)
#include <cuda_runtime.h>
#include <cuda_bf16.h>
#include <math_constants.h>

// Problem constants
#define NTOK 8192
#define DIM  1024
#define DK   128
#define DV   128

// Scratch for projections (device globals: allocation-free)
__device__ float g_qk[NTOK * DK];
__device__ float g_v[NTOK * DV];

// ---------------------------------------------------------------------------
// Projection kernel: out[n, c] = sum_d x[n,d] * W[c,d] + b[c]
// Block computes 64 rows x 128 cols. blockIdx.y selects (Wqk,bqk)->g_qk or (Wv,bv)->g_v.
// ---------------------------------------------------------------------------
__global__ __launch_bounds__(256, 2)
void proj_kernel(const float* __restrict__ x,
                 const float* __restrict__ Wqk, const float* __restrict__ bqk,
                 const float* __restrict__ Wv,  const float* __restrict__ bv) {
    const int row0 = blockIdx.x * 64;
    const float* W;  const float* bias;  float* out;
    if (blockIdx.y == 0) { W = Wqk; bias = bqk; out = g_qk; }
    else                 { W = Wv;  bias = bv;  out = g_v;  }

    __shared__ float sxT[32][68];    // [k][row]  64 rows
    __shared__ float swT[32][132];   // [k][col] 128 cols

    const int tid = threadIdx.x;
    const int tx = tid & 15;         // col group: cols tx*8 .. tx*8+7
    const int ty = tid >> 4;         // row group: rows ty*4 .. ty*4+3

    float acc[4][8];
#pragma unroll
    for (int i = 0; i < 4; i++)
#pragma unroll
        for (int j = 0; j < 8; j++) acc[i][j] = 0.f;

    for (int kk = 0; kk < DIM; kk += 32) {
        __syncthreads();
        // x tile -> transposed smem (lanes vary row -> conflict-free STS)
#pragma unroll
        for (int it = 0; it < 2; it++) {
            int idx = it * 256 + tid;
            int r = idx & 63, kq = idx >> 6;            // kq in 0..7
            float4 g = *(const float4*)&x[(size_t)(row0 + r) * DIM + kk + kq * 4];
            sxT[kq * 4 + 0][r] = g.x; sxT[kq * 4 + 1][r] = g.y;
            sxT[kq * 4 + 2][r] = g.z; sxT[kq * 4 + 3][r] = g.w;
        }
        // W tile -> transposed smem
#pragma unroll
        for (int it = 0; it < 4; it++) {
            int idx = it * 256 + tid;
            int c = idx & 127, kq = idx >> 7;           // kq in 0..7
            float4 g = *(const float4*)&W[(size_t)c * DIM + kk + kq * 4];
            swT[kq * 4 + 0][c] = g.x; swT[kq * 4 + 1][c] = g.y;
            swT[kq * 4 + 2][c] = g.z; swT[kq * 4 + 3][c] = g.w;
        }
        __syncthreads();

#pragma unroll 8
        for (int k = 0; k < 32; k++) {
            const float4 a = *(const float4*)&sxT[k][ty << 2];
            const float4 b0 = *(const float4*)&swT[k][tx << 3];
            const float4 b1 = *(const float4*)&swT[k][(tx << 3) + 4];
            const float av[4] = {a.x, a.y, a.z, a.w};
            const float bv8[8] = {b0.x, b0.y, b0.z, b0.w, b1.x, b1.y, b1.z, b1.w};
#pragma unroll
            for (int i = 0; i < 4; i++)
#pragma unroll
                for (int j = 0; j < 8; j++) acc[i][j] += av[i] * bv8[j];
        }
    }

    // epilogue with bias
    float bb[8];
#pragma unroll
    for (int j = 0; j < 8; j++) bb[j] = bias[(tx << 3) + j];
#pragma unroll
    for (int i = 0; i < 4; i++) {
        int r = row0 + (ty << 2) + i;
        float4 o0 = make_float4(acc[i][0] + bb[0], acc[i][1] + bb[1], acc[i][2] + bb[2], acc[i][3] + bb[3]);
        float4 o1 = make_float4(acc[i][4] + bb[4], acc[i][5] + bb[5], acc[i][6] + bb[6], acc[i][7] + bb[7]);
        *(float4*)&out[(size_t)r * DK + (tx << 3)]     = o0;
        *(float4*)&out[(size_t)r * DK + (tx << 3) + 4] = o1;
    }
}

// ---------------------------------------------------------------------------
// Flash attention kernel: Q = K = g_qk, V = g_v. BM=64 rows per block, BN=64 keys/tile.
// smem layout (dynamic):
//   Qt [128][68]  transposed Q tile
//   Kt [128][68]  transposed K tile
//   Vs [64][132]  row-major V tile
//   Ps [64][65]   probabilities
// ---------------------------------------------------------------------------
#define QT_LD 68
#define VS_LD 132
#define PS_LD 65
#define SM_QT 0
#define SM_KT (SM_QT + 128 * QT_LD)
#define SM_VS (SM_KT + 128 * QT_LD)
#define SM_PS (SM_VS + 64 * VS_LD)
#define FLASH_SMEM ((SM_PS + 64 * PS_LD) * sizeof(float))

__global__ __launch_bounds__(256, 1)
void flash_kernel(float* __restrict__ out) {
    extern __shared__ float sm[];
    float* Qt = sm + SM_QT;
    float* Kt = sm + SM_KT;
    float* Vs = sm + SM_VS;
    float* Ps = sm + SM_PS;

    const int row0 = blockIdx.x * 64;
    const int tid = threadIdx.x;
    const int tx = tid & 15;    // key-col group (4 cols) / out-col group (8 cols)
    const int ty = tid >> 4;    // row group (4 rows)

    // Load Q tile transposed (once). Lanes vary row -> conflict-free STS.
#pragma unroll
    for (int it = 0; it < 8; it++) {
        int idx = it * 256 + tid;
        int r = idx & 63, kq = idx >> 6;                // kq 0..31
        float4 g = *(const float4*)&g_qk[(size_t)(row0 + r) * DK + kq * 4];
        Qt[(kq * 4 + 0) * QT_LD + r] = g.x; Qt[(kq * 4 + 1) * QT_LD + r] = g.y;
        Qt[(kq * 4 + 2) * QT_LD + r] = g.z; Qt[(kq * 4 + 3) * QT_LD + r] = g.w;
    }

    float m[4], l[4], o[4][8];
#pragma unroll
    for (int i = 0; i < 4; i++) {
        m[i] = -CUDART_INF_F; l[i] = 0.f;
#pragma unroll
        for (int d = 0; d < 8; d++) o[i][d] = 0.f;
    }

    for (int j0 = 0; j0 < NTOK; j0 += 64) {
        __syncthreads();
        // K tile transposed
#pragma unroll
        for (int it = 0; it < 8; it++) {
            int idx = it * 256 + tid;
            int r = idx & 63, kq = idx >> 6;
            float4 g = *(const float4*)&g_qk[(size_t)(j0 + r) * DK + kq * 4];
            Kt[(kq * 4 + 0) * QT_LD + r] = g.x; Kt[(kq * 4 + 1) * QT_LD + r] = g.y;
            Kt[(kq * 4 + 2) * QT_LD + r] = g.z; Kt[(kq * 4 + 3) * QT_LD + r] = g.w;
        }
        // V tile row-major (coalesced both sides)
#pragma unroll
        for (int it = 0; it < 8; it++) {
            int idx = it * 256 + tid;
            int jr = idx >> 5, kq = idx & 31;
            float4 g = *(const float4*)&g_v[(size_t)(j0 + jr) * DV + kq * 4];
            *(float4*)&Vs[jr * VS_LD + kq * 4] = g;
        }
        __syncthreads();

        // S = Q K^T  (4x4 per thread)
        float s[4][4];
#pragma unroll
        for (int i = 0; i < 4; i++)
#pragma unroll
            for (int j = 0; j < 4; j++) s[i][j] = 0.f;

#pragma unroll 8
        for (int k = 0; k < 128; k++) {
            const float4 a = *(const float4*)&Qt[k * QT_LD + (ty << 2)];
            const float4 b = *(const float4*)&Kt[k * QT_LD + (tx << 2)];
            const float av[4] = {a.x, a.y, a.z, a.w};
            const float bv4[4] = {b.x, b.y, b.z, b.w};
#pragma unroll
            for (int i = 0; i < 4; i++)
#pragma unroll
                for (int j = 0; j < 4; j++) s[i][j] += av[i] * bv4[j];
        }

        // Online softmax (row reductions across 16 lanes of same ty, width-16 shuffles)
#pragma unroll
        for (int i = 0; i < 4; i++) {
            float tmax = fmaxf(fmaxf(s[i][0], s[i][1]), fmaxf(s[i][2], s[i][3]));
#pragma unroll
            for (int off = 8; off >= 1; off >>= 1)
                tmax = fmaxf(tmax, __shfl_xor_sync(0xffffffffu, tmax, off, 16));
            const float newm = fmaxf(m[i], tmax);
            const float alpha = __expf(m[i] - newm);
            float psum = 0.f;
            const int prow = ((ty << 2) + i) * PS_LD;
#pragma unroll
            for (int j = 0; j < 4; j++) {
                float p = __expf(s[i][j] - newm);
                Ps[prow + (tx << 2) + j] = p;
                psum += p;
            }
#pragma unroll
            for (int off = 8; off >= 1; off >>= 1)
                psum += __shfl_xor_sync(0xffffffffu, psum, off, 16);
            l[i] = l[i] * alpha + psum;
            m[i] = newm;
#pragma unroll
            for (int d = 0; d < 8; d++) o[i][d] *= alpha;
        }
        __syncwarp();   // Ps rows are produced & consumed within one warp

        // O += P * V
#pragma unroll 2
        for (int j = 0; j < 64; j++) {
            const float4 v0 = *(const float4*)&Vs[j * VS_LD + (tx << 3)];
            const float4 v1 = *(const float4*)&Vs[j * VS_LD + (tx << 3) + 4];
#pragma unroll
            for (int i = 0; i < 4; i++) {
                const float p = Ps[((ty << 2) + i) * PS_LD + j];
                o[i][0] += p * v0.x; o[i][1] += p * v0.y;
                o[i][2] += p * v0.z; o[i][3] += p * v0.w;
                o[i][4] += p * v1.x; o[i][5] += p * v1.y;
                o[i][6] += p * v1.z; o[i][7] += p * v1.w;
            }
        }
    }

    // Epilogue: normalize and store
#pragma unroll
    for (int i = 0; i < 4; i++) {
        const float inv = 1.f / l[i];
        const int r = row0 + (ty << 2) + i;
        float4 o0 = make_float4(o[i][0] * inv, o[i][1] * inv, o[i][2] * inv, o[i][3] * inv);
        float4 o1 = make_float4(o[i][4] * inv, o[i][5] * inv, o[i][6] * inv, o[i][7] * inv);
        *(float4*)&out[(size_t)r * DV + (tx << 3)]     = o0;
        *(float4*)&out[(size_t)r * DV + (tx << 3) + 4] = o1;
    }
}

// ---------------------------------------------------------------------------
extern "C" void kernel_launch(void* const* d_in, const int* in_sizes, int n_in,
                              void* d_out, int out_size) {
    const float* x   = (const float*)d_in[0];
    const float* Wqk = (const float*)d_in[1];
    const float* bqk = (const float*)d_in[2];
    const float* Wv  = (const float*)d_in[3];
    const float* bv  = (const float*)d_in[4];
    float* out = (float*)d_out;

    cudaFuncSetAttribute(flash_kernel, cudaFuncAttributeMaxDynamicSharedMemorySize,
                         (int)FLASH_SMEM);

    proj_kernel<<<dim3(NTOK / 64, 2), 256>>>(x, Wqk, bqk, Wv, bv);
    flash_kernel<<<NTOK / 64, 256, FLASH_SMEM>>>(out);
}

// round 4
// speedup vs baseline: 4.0445x; 4.0445x over previous
#include <cuda_runtime.h>
#include <cuda_bf16.h>
#include <stdint.h>

#define NTOK 8192
#define DIM  1024
#define DK   128
#define DV   128

// ---------------- device globals (allocation-free scratch) ----------------
__device__ float g_qk[NTOK * DK];
__device__ float g_v[NTOK * DV];
__device__ __align__(256) __nv_bfloat16 g_qkh[NTOK * DK];   // qk bf16 row-major
__device__ __align__(256) float g_ss[NTOK];                 // ||qk_i||^2 fp32
__device__ __align__(256) float g_O[2][NTOK * DV];          // split-KV numerators
__device__ __align__(256) float g_l[2][NTOK];               // split-KV denominators

// ---------------- helpers ----------------
__device__ __forceinline__ uint32_t smem_to_u32(const void* p) {
    uint32_t a;
    asm("{ .reg .u64 t; cvta.to.shared.u64 t, %1; cvt.u32.u64 %0, t; }" : "=r"(a) : "l"(p));
    return a;
}
__device__ __forceinline__ void cp16(uint32_t dst, const void* src) {
    asm volatile("cp.async.cg.shared.global [%0], [%1], 16;" :: "r"(dst), "l"(src) : "memory");
}
#define CP_COMMIT() asm volatile("cp.async.commit_group;" ::: "memory")
#define CP_WAIT0()  asm volatile("cp.async.wait_group 0;" ::: "memory")

__device__ __forceinline__ uint32_t bf2_to_u32(__nv_bfloat162 v) {
    uint32_t u; *(__nv_bfloat162*)&u = v; return u;
}

#define LDSM_X4(r0, r1, r2, r3, a) \
    asm volatile("ldmatrix.sync.aligned.m8n8.x4.shared.b16 {%0,%1,%2,%3}, [%4];" \
                 : "=r"(r0), "=r"(r1), "=r"(r2), "=r"(r3) : "r"(a))
#define LDSM_X2_T(r0, r1, a) \
    asm volatile("ldmatrix.sync.aligned.m8n8.x2.trans.shared.b16 {%0,%1}, [%2];" \
                 : "=r"(r0), "=r"(r1) : "r"(a))
// D(f32 4) += A(bf16 16x16) * B(bf16 16x8 col)
#define MMA16816(d, a, b0, b1) \
    asm volatile("mma.sync.aligned.m16n8k16.row.col.f32.bf16.bf16.f32 " \
                 "{%0,%1,%2,%3}, {%4,%5,%6,%7}, {%8,%9}, {%0,%1,%2,%3};" \
                 : "+f"((d)[0]), "+f"((d)[1]), "+f"((d)[2]), "+f"((d)[3]) \
                 : "r"((a)[0]), "r"((a)[1]), "r"((a)[2]), "r"((a)[3]), "r"(b0), "r"(b1))

// ============================================================================
// proj (FFMA, proven): out[n,c] = x[n]·W[c] + b[c]
// ============================================================================
__global__ __launch_bounds__(256, 2)
void proj_kernel(const float* __restrict__ x,
                 const float* __restrict__ Wqk, const float* __restrict__ bqk,
                 const float* __restrict__ Wv,  const float* __restrict__ bv) {
    const int row0 = blockIdx.x * 64;
    const float* W;  const float* bias;  float* out;
    if (blockIdx.y == 0) { W = Wqk; bias = bqk; out = g_qk; }
    else                 { W = Wv;  bias = bv;  out = g_v;  }

    __shared__ float sxT[32][68];
    __shared__ float swT[32][132];

    const int tid = threadIdx.x;
    const int tx = tid & 15;
    const int ty = tid >> 4;

    float acc[4][8];
#pragma unroll
    for (int i = 0; i < 4; i++)
#pragma unroll
        for (int j = 0; j < 8; j++) acc[i][j] = 0.f;

    for (int kk = 0; kk < DIM; kk += 32) {
        __syncthreads();
#pragma unroll
        for (int it = 0; it < 2; it++) {
            int idx = it * 256 + tid;
            int r = idx & 63, kq = idx >> 6;
            float4 g = *(const float4*)&x[(size_t)(row0 + r) * DIM + kk + kq * 4];
            sxT[kq * 4 + 0][r] = g.x; sxT[kq * 4 + 1][r] = g.y;
            sxT[kq * 4 + 2][r] = g.z; sxT[kq * 4 + 3][r] = g.w;
        }
#pragma unroll
        for (int it = 0; it < 4; it++) {
            int idx = it * 256 + tid;
            int c = idx & 127, kq = idx >> 7;
            float4 g = *(const float4*)&W[(size_t)c * DIM + kk + kq * 4];
            swT[kq * 4 + 0][c] = g.x; swT[kq * 4 + 1][c] = g.y;
            swT[kq * 4 + 2][c] = g.z; swT[kq * 4 + 3][c] = g.w;
        }
        __syncthreads();

#pragma unroll 8
        for (int k = 0; k < 32; k++) {
            const float4 a = *(const float4*)&sxT[k][ty << 2];
            const float4 b0 = *(const float4*)&swT[k][tx << 3];
            const float4 b1 = *(const float4*)&swT[k][(tx << 3) + 4];
            const float av[4] = {a.x, a.y, a.z, a.w};
            const float bv8[8] = {b0.x, b0.y, b0.z, b0.w, b1.x, b1.y, b1.z, b1.w};
#pragma unroll
            for (int i = 0; i < 4; i++)
#pragma unroll
                for (int j = 0; j < 8; j++) acc[i][j] += av[i] * bv8[j];
        }
    }

    float bb[8];
#pragma unroll
    for (int j = 0; j < 8; j++) bb[j] = bias[(tx << 3) + j];
#pragma unroll
    for (int i = 0; i < 4; i++) {
        int r = row0 + (ty << 2) + i;
        float4 o0 = make_float4(acc[i][0] + bb[0], acc[i][1] + bb[1], acc[i][2] + bb[2], acc[i][3] + bb[3]);
        float4 o1 = make_float4(acc[i][4] + bb[4], acc[i][5] + bb[5], acc[i][6] + bb[6], acc[i][7] + bb[7]);
        *(float4*)&out[(size_t)r * DK + (tx << 3)]     = o0;
        *(float4*)&out[(size_t)r * DK + (tx << 3) + 4] = o1;
    }
}

// ============================================================================
// prep: g_qk -> g_qkh (bf16) + g_ss (fp32 row norms). grid 64, 256 thr.
// ============================================================================
__global__ __launch_bounds__(256, 4)
void prep_kernel() {
    const int tid = threadIdx.x;
    const int r0 = blockIdx.x * 128;
    const int row = tid >> 1, half = tid & 1;
    const float* src = &g_qk[(size_t)(r0 + row) * DK + half * 64];
    __nv_bfloat16* dst = &g_qkh[(size_t)(r0 + row) * DK + half * 64];
    float ss = 0.f;
#pragma unroll
    for (int i = 0; i < 16; i++) {
        float4 f = *(const float4*)&src[i * 4];
        ss += f.x * f.x + f.y * f.y + f.z * f.z + f.w * f.w;
        uint2 u;
        u.x = bf2_to_u32(__floats2bfloat162_rn(f.x, f.y));
        u.y = bf2_to_u32(__floats2bfloat162_rn(f.z, f.w));
        *(uint2*)&dst[i * 4] = u;
    }
    ss += __shfl_xor_sync(0xffffffffu, ss, 1);
    if (half == 0) g_ss[r0 + row] = ss;
}

// ============================================================================
// attention (HMMA): BM=128 (16 rows/warp), BN=128, split-KV x2.
// smem: K0/K1 double-buffered bf16 tiles, VH/VL lazy hi/lo bf16 V tiles.
// ============================================================================
#define LDV 136          // bf16 per smem row (pad 8)
#define ROWB (LDV * 2)   // 272 bytes per row
#define AT_K0 0
#define AT_K1 34816
#define AT_VH 69632
#define AT_VL 104448
#define AT_FLAGS 139264
#define ATT_SMEM (AT_FLAGS + 64)

__global__ __launch_bounds__(256, 1)
void attn_kernel() {
    extern __shared__ char smem[];
    const uint32_t sb = smem_to_u32(smem);
    int* flags = (int*)(smem + AT_FLAGS);
    const int tid = threadIdx.x, wid = tid >> 5, lane = tid & 31;
    const int row0 = blockIdx.x * 128;
    const int h = blockIdx.y;
    const int j0base = h * 4096;

    // ldmatrix per-thread address pieces
    const int rA = ((lane >> 3) & 1) * 8 + (lane & 7);  // A-frag / V-frag row-in-16
    const int kA = (lane >> 4) & 1;                      // A-frag k-half
    const int rB = ((lane >> 4) & 1) * 8 + (lane & 7);  // K B-frag row-in-16
    const int kB = (lane >> 3) & 1;                      // K B-frag k-half

    const int rl = row0 + wid * 16 + (lane >> 2);
    const int rh = rl + 8;
    const float m0 = g_ss[rl], m1 = g_ss[rh];
    const float thr0 = m0 - 20.f, thr1 = m1 - 20.f;

    // Load Q (into VH region, temporarily) and K tile 0
#pragma unroll
    for (int it = 0; it < 8; it++) {
        int c = it * 256 + tid;
        int r = c >> 4, cc = (c & 15) * 8;
        cp16(sb + AT_VH + r * ROWB + cc * 2, &g_qkh[(size_t)(row0 + r) * DK + cc]);
        cp16(sb + AT_K0 + r * ROWB + cc * 2, &g_qkh[(size_t)(j0base + r) * DK + cc]);
    }
    CP_COMMIT(); CP_WAIT0();
    __syncthreads();

    // Build Q A-fragments once (reused for all 32 K tiles)
    uint32_t qa[8][4];
    {
        const uint32_t qrow = sb + AT_VH + (uint32_t)(wid * 16 + rA) * ROWB;
#pragma unroll
        for (int s = 0; s < 8; s++)
            LDSM_X4(qa[s][0], qa[s][1], qa[s][2], qa[s][3], qrow + (s * 16 + kA * 8) * 2);
    }
    __syncthreads();   // Q reads done before VH may be overwritten by V

    float oa[16][4];
#pragma unroll
    for (int nt = 0; nt < 16; nt++)
#pragma unroll
        for (int q = 0; q < 4; q++) oa[nt][q] = 0.f;
    float l0 = 0.f, l1 = 0.f;

    for (int t = 0; t < 32; t++) {
        if (t > 0) CP_WAIT0();
        __syncthreads();   // K(t) ready; previous tile fully consumed

        // prefetch K(t+1) into the other buffer
        if (t + 1 < 32) {
            const uint32_t nb = sb + ((t & 1) ? AT_K0 : AT_K1);
            const int j1 = j0base + (t + 1) * 128;
#pragma unroll
            for (int it = 0; it < 8; it++) {
                int c = it * 256 + tid;
                int r = c >> 4, cc = (c & 15) * 8;
                cp16(nb + r * ROWB + cc * 2, &g_qkh[(size_t)(j1 + r) * DK + cc]);
            }
            CP_COMMIT();
        }

        // S = Q K^T for this tile (per warp: 16 rows x 128 keys)
        const uint32_t kb = sb + ((t & 1) ? AT_K1 : AT_K0);
        float sa[16][4];
#pragma unroll
        for (int nt = 0; nt < 16; nt++)
#pragma unroll
            for (int q = 0; q < 4; q++) sa[nt][q] = 0.f;
#pragma unroll
        for (int np = 0; np < 8; np++) {
            const uint32_t krow = kb + (uint32_t)(np * 16 + rB) * ROWB;
#pragma unroll
            for (int s = 0; s < 8; s++) {
                uint32_t b0, b1, b2, b3;
                LDSM_X4(b0, b1, b2, b3, krow + (s * 16 + kB * 8) * 2);
                MMA16816(sa[2 * np],     qa[s], b0, b1);
                MMA16816(sa[2 * np + 1], qa[s], b2, b3);
            }
        }

        // row maxes (two rows per thread; quad lanes share a row)
        float mx0 = -3.0e38f, mx1 = -3.0e38f;
#pragma unroll
        for (int nt = 0; nt < 16; nt++) {
            mx0 = fmaxf(mx0, fmaxf(sa[nt][0], sa[nt][1]));
            mx1 = fmaxf(mx1, fmaxf(sa[nt][2], sa[nt][3]));
        }
        mx0 = fmaxf(mx0, __shfl_xor_sync(0xffffffffu, mx0, 1));
        mx0 = fmaxf(mx0, __shfl_xor_sync(0xffffffffu, mx0, 2));
        mx1 = fmaxf(mx1, __shfl_xor_sync(0xffffffffu, mx1, 1));
        mx1 = fmaxf(mx1, __shfl_xor_sync(0xffffffffu, mx1, 2));
        const bool act0 = mx0 >= thr0, act1 = mx1 >= thr1;
        const int wact = __any_sync(0xffffffffu, act0 || act1);
        if (lane == 0) flags[wid] = wact;
        __syncthreads();
        int cact = 0;
#pragma unroll
        for (int w = 0; w < 8; w++) cact |= flags[w];

        if (cact) {
            // lazy V tile load: fp32 -> bf16 hi/lo into VH/VL
            const int j0 = j0base + t * 128;
#pragma unroll
            for (int it = 0; it < 16; it++) {
                int idx = it * 256 + tid;
                int r = idx >> 5, cq = (idx & 31) * 4;
                float4 f = *(const float4*)&g_v[(size_t)(j0 + r) * DV + cq];
                __nv_bfloat162 h0 = __floats2bfloat162_rn(f.x, f.y);
                __nv_bfloat162 h1 = __floats2bfloat162_rn(f.z, f.w);
                __nv_bfloat162 e0 = __floats2bfloat162_rn(f.x - __bfloat162float(h0.x),
                                                          f.y - __bfloat162float(h0.y));
                __nv_bfloat162 e1 = __floats2bfloat162_rn(f.z - __bfloat162float(h1.x),
                                                          f.w - __bfloat162float(h1.y));
                uint2 uh; uh.x = bf2_to_u32(h0); uh.y = bf2_to_u32(h1);
                uint2 ul; ul.x = bf2_to_u32(e0); ul.y = bf2_to_u32(e1);
                *(uint2*)(smem + AT_VH + r * ROWB + cq * 2) = uh;
                *(uint2*)(smem + AT_VL + r * ROWB + cq * 2) = ul;
            }
            __syncthreads();

            if (wact) {
#pragma unroll
                for (int s = 0; s < 8; s++) {
                    // P fragments from exp(S - m); l accumulates the SAME rounded p
                    uint32_t pa[4];
                    float e00 = act0 ? __expf(sa[2 * s][0] - m0) : 0.f;
                    float e01 = act0 ? __expf(sa[2 * s][1] - m0) : 0.f;
                    float e10 = act1 ? __expf(sa[2 * s][2] - m1) : 0.f;
                    float e11 = act1 ? __expf(sa[2 * s][3] - m1) : 0.f;
                    float f00 = act0 ? __expf(sa[2 * s + 1][0] - m0) : 0.f;
                    float f01 = act0 ? __expf(sa[2 * s + 1][1] - m0) : 0.f;
                    float f10 = act1 ? __expf(sa[2 * s + 1][2] - m1) : 0.f;
                    float f11 = act1 ? __expf(sa[2 * s + 1][3] - m1) : 0.f;
                    __nv_bfloat162 b;
                    b = __floats2bfloat162_rn(e00, e01); pa[0] = bf2_to_u32(b);
                    l0 += __bfloat162float(b.x) + __bfloat162float(b.y);
                    b = __floats2bfloat162_rn(e10, e11); pa[1] = bf2_to_u32(b);
                    l1 += __bfloat162float(b.x) + __bfloat162float(b.y);
                    b = __floats2bfloat162_rn(f00, f01); pa[2] = bf2_to_u32(b);
                    l0 += __bfloat162float(b.x) + __bfloat162float(b.y);
                    b = __floats2bfloat162_rn(f10, f11); pa[3] = bf2_to_u32(b);
                    l1 += __bfloat162float(b.x) + __bfloat162float(b.y);

                    const uint32_t vrow = (uint32_t)(s * 16 + rA) * ROWB;
#pragma unroll
                    for (int nt = 0; nt < 16; nt++) {
                        uint32_t bh0, bh1, bl0, bl1;
                        LDSM_X2_T(bh0, bh1, sb + AT_VH + vrow + nt * 16);
                        MMA16816(oa[nt], pa, bh0, bh1);
                        LDSM_X2_T(bl0, bl1, sb + AT_VL + vrow + nt * 16);
                        MMA16816(oa[nt], pa, bl0, bl1);
                    }
                }
            }
        }
    }

    // epilogue: write split-KV numerators + denominators
    l0 += __shfl_xor_sync(0xffffffffu, l0, 1);
    l0 += __shfl_xor_sync(0xffffffffu, l0, 2);
    l1 += __shfl_xor_sync(0xffffffffu, l1, 1);
    l1 += __shfl_xor_sync(0xffffffffu, l1, 2);
#pragma unroll
    for (int nt = 0; nt < 16; nt++) {
        const int col = nt * 8 + 2 * (lane & 3);
        float2 v0; v0.x = oa[nt][0]; v0.y = oa[nt][1];
        float2 v1; v1.x = oa[nt][2]; v1.y = oa[nt][3];
        *(float2*)&g_O[h][(size_t)rl * DV + col] = v0;
        *(float2*)&g_O[h][(size_t)rh * DV + col] = v1;
    }
    if ((lane & 3) == 0) {
        g_l[h][rl] = l0;
        g_l[h][rh] = l1;
    }
}

// ============================================================================
// combine: out = (O0 + O1) / (l0 + l1)
// ============================================================================
__global__ __launch_bounds__(256, 4)
void combine_kernel(float* __restrict__ out) {
    const int i4 = blockIdx.x * 256 + threadIdx.x;
    const int rowi = i4 >> 5;
    const float inv = 1.0f / (g_l[0][rowi] + g_l[1][rowi]);
    float4 a = ((const float4*)g_O[0])[i4];
    float4 b = ((const float4*)g_O[1])[i4];
    float4 o = make_float4((a.x + b.x) * inv, (a.y + b.y) * inv,
                           (a.z + b.z) * inv, (a.w + b.w) * inv);
    ((float4*)out)[i4] = o;
}

// ---------------------------------------------------------------------------
extern "C" void kernel_launch(void* const* d_in, const int* in_sizes, int n_in,
                              void* d_out, int out_size) {
    const float* x   = (const float*)d_in[0];
    const float* Wqk = (const float*)d_in[1];
    const float* bqk = (const float*)d_in[2];
    const float* Wv  = (const float*)d_in[3];
    const float* bv  = (const float*)d_in[4];
    float* out = (float*)d_out;

    cudaFuncSetAttribute(attn_kernel, cudaFuncAttributeMaxDynamicSharedMemorySize, ATT_SMEM);

    proj_kernel<<<dim3(NTOK / 64, 2), 256>>>(x, Wqk, bqk, Wv, bv);
    prep_kernel<<<NTOK / 128, 256>>>();
    attn_kernel<<<dim3(NTOK / 128, 2), 256, ATT_SMEM>>>();
    combine_kernel<<<1024, 256>>>(out);
}

// round 5
// speedup vs baseline: 7.1097x; 1.7579x over previous
#include <cuda_runtime.h>
#include <cuda_bf16.h>
#include <stdint.h>

#define NTOK 8192
#define DIM  1024
#define DK   128
#define DV   128

// ---------------- device globals (allocation-free scratch) ----------------
__device__ float g_v[NTOK * DV];
__device__ __align__(256) __nv_bfloat16 g_qkh[NTOK * DK];   // qk bf16 row-major
__device__ __align__(256) float g_ss[NTOK];                 // ||qk_i||^2 fp32
__device__ __align__(256) float g_O[2][NTOK * DV];          // split-KV numerators
__device__ __align__(256) float g_l[2][NTOK];               // split-KV denominators

// ---------------- helpers ----------------
__device__ __forceinline__ uint32_t smem_to_u32(const void* p) {
    uint32_t a;
    asm("{ .reg .u64 t; cvta.to.shared.u64 t, %1; cvt.u32.u64 %0, t; }" : "=r"(a) : "l"(p));
    return a;
}
__device__ __forceinline__ void cp16(uint32_t dst, const void* src) {
    asm volatile("cp.async.cg.shared.global [%0], [%1], 16;" :: "r"(dst), "l"(src) : "memory");
}
#define CP_COMMIT() asm volatile("cp.async.commit_group;" ::: "memory")
#define CP_WAIT0()  asm volatile("cp.async.wait_group 0;" ::: "memory")

__device__ __forceinline__ uint32_t bf2_to_u32(__nv_bfloat162 v) {
    uint32_t u; *(__nv_bfloat162*)&u = v; return u;
}

#define LDSM_X4(r0, r1, r2, r3, a) \
    asm volatile("ldmatrix.sync.aligned.m8n8.x4.shared.b16 {%0,%1,%2,%3}, [%4];" \
                 : "=r"(r0), "=r"(r1), "=r"(r2), "=r"(r3) : "r"(a))
#define LDSM_X2_T(r0, r1, a) \
    asm volatile("ldmatrix.sync.aligned.m8n8.x2.trans.shared.b16 {%0,%1}, [%2];" \
                 : "=r"(r0), "=r"(r1) : "r"(a))
// D(f32 4) += A(bf16 16x16) * B(bf16 16x8 col)
#define MMA16816(d, a, b0, b1) \
    asm volatile("mma.sync.aligned.m16n8k16.row.col.f32.bf16.bf16.f32 " \
                 "{%0,%1,%2,%3}, {%4,%5,%6,%7}, {%8,%9}, {%0,%1,%2,%3};" \
                 : "+f"((d)[0]), "+f"((d)[1]), "+f"((d)[2]), "+f"((d)[3]) \
                 : "r"((a)[0]), "r"((a)[1]), "r"((a)[2]), "r"((a)[3]), "r"(b0), "r"(b1))

// ============================================================================
// proj (HMMA, bf16 hi/lo 3-product split): out[n,c] = x[n]·W[c] + b[c]
// grid (64, 2): 128 rows x 128 cols per CTA; y: 0 -> qk (writes g_qkh+g_ss),
//                                             1 -> v (writes g_v fp32)
// smem: Ah/Al/Bh/Bl bf16 tiles (144B pitch rows) + fp32 staging SA/SB.
// ============================================================================
#define PJ_ROWB 144
#define PJ_AH 0
#define PJ_AL 18432
#define PJ_BH 36864
#define PJ_BL 55296
#define PJ_SA 73728
#define PJ_SB 106496
#define PJ_SMEM 139264

__global__ __launch_bounds__(256, 1)
void proj_hmma_kernel(const float* __restrict__ x,
                      const float* __restrict__ Wqk, const float* __restrict__ bqk,
                      const float* __restrict__ Wv,  const float* __restrict__ bv) {
    extern __shared__ char smem[];
    const uint32_t sb = smem_to_u32(smem);
    const int tid = threadIdx.x, wid = tid >> 5, lane = tid & 31;
    const int row0 = blockIdx.x * 128;
    const int type = blockIdx.y;
    const float* W = type ? Wv : Wqk;
    const float* bias = type ? bv : bqk;

    // ldmatrix lane mappings (identical to attn S-GEMM, proven round 4)
    const int rA = ((lane >> 3) & 1) * 8 + (lane & 7);
    const int kA = (lane >> 4) & 1;
    const int rB = ((lane >> 4) & 1) * 8 + (lane & 7);
    const int kB = (lane >> 3) & 1;

    float acc[16][4];
#pragma unroll
    for (int nt = 0; nt < 16; nt++)
#pragma unroll
        for (int q = 0; q < 4; q++) acc[nt][q] = 0.f;

    // preload chunk 0 into fp32 staging
#pragma unroll
    for (int it = 0; it < 8; it++) {
        int idx = it * 256 + tid;
        int r = idx >> 4, kq = (idx & 15) * 4;
        cp16(sb + PJ_SA + r * 256 + kq * 4, &x[(size_t)(row0 + r) * DIM + kq]);
        cp16(sb + PJ_SB + r * 256 + kq * 4, &W[(size_t)r * DIM + kq]);
    }
    CP_COMMIT();

    for (int c = 0; c < 16; c++) {
        CP_WAIT0();
        __syncthreads();   // staging ready; prior MMAs done reading bf16 tiles

        // convert fp32 staging -> bf16 hi/lo tiles
#pragma unroll
        for (int it = 0; it < 8; it++) {
            int idx = it * 256 + tid;
            int r = idx >> 4, kq = (idx & 15) * 4;
            float4 fa = *(const float4*)(smem + PJ_SA + r * 256 + kq * 4);
            float4 fb = *(const float4*)(smem + PJ_SB + r * 256 + kq * 4);
            __nv_bfloat162 ah0 = __floats2bfloat162_rn(fa.x, fa.y);
            __nv_bfloat162 ah1 = __floats2bfloat162_rn(fa.z, fa.w);
            __nv_bfloat162 al0 = __floats2bfloat162_rn(fa.x - __bfloat162float(ah0.x),
                                                       fa.y - __bfloat162float(ah0.y));
            __nv_bfloat162 al1 = __floats2bfloat162_rn(fa.z - __bfloat162float(ah1.x),
                                                       fa.w - __bfloat162float(ah1.y));
            __nv_bfloat162 bh0 = __floats2bfloat162_rn(fb.x, fb.y);
            __nv_bfloat162 bh1 = __floats2bfloat162_rn(fb.z, fb.w);
            __nv_bfloat162 bl0 = __floats2bfloat162_rn(fb.x - __bfloat162float(bh0.x),
                                                       fb.y - __bfloat162float(bh0.y));
            __nv_bfloat162 bl1 = __floats2bfloat162_rn(fb.z - __bfloat162float(bh1.x),
                                                       fb.w - __bfloat162float(bh1.y));
            uint2 u;
            u.x = bf2_to_u32(ah0); u.y = bf2_to_u32(ah1);
            *(uint2*)(smem + PJ_AH + r * PJ_ROWB + kq * 2) = u;
            u.x = bf2_to_u32(al0); u.y = bf2_to_u32(al1);
            *(uint2*)(smem + PJ_AL + r * PJ_ROWB + kq * 2) = u;
            u.x = bf2_to_u32(bh0); u.y = bf2_to_u32(bh1);
            *(uint2*)(smem + PJ_BH + r * PJ_ROWB + kq * 2) = u;
            u.x = bf2_to_u32(bl0); u.y = bf2_to_u32(bl1);
            *(uint2*)(smem + PJ_BL + r * PJ_ROWB + kq * 2) = u;
        }
        __syncthreads();

        // prefetch next chunk into staging (overlaps MMA below)
        if (c + 1 < 16) {
            const int kk = (c + 1) * 64;
#pragma unroll
            for (int it = 0; it < 8; it++) {
                int idx = it * 256 + tid;
                int r = idx >> 4, kq = (idx & 15) * 4;
                cp16(sb + PJ_SA + r * 256 + kq * 4, &x[(size_t)(row0 + r) * DIM + kk + kq]);
                cp16(sb + PJ_SB + r * 256 + kq * 4, &W[(size_t)r * DIM + kk + kq]);
            }
            CP_COMMIT();
        }

        // A fragments (hi & lo) for this warp's 16 rows, 4 k-steps
        uint32_t ah[4][4], al[4][4];
        const uint32_t arh = sb + PJ_AH + (uint32_t)(wid * 16 + rA) * PJ_ROWB;
        const uint32_t arl = sb + PJ_AL + (uint32_t)(wid * 16 + rA) * PJ_ROWB;
#pragma unroll
        for (int s = 0; s < 4; s++) {
            LDSM_X4(ah[s][0], ah[s][1], ah[s][2], ah[s][3], arh + (s * 16 + kA * 8) * 2);
            LDSM_X4(al[s][0], al[s][1], al[s][2], al[s][3], arl + (s * 16 + kA * 8) * 2);
        }

#pragma unroll
        for (int s = 0; s < 4; s++) {
#pragma unroll
            for (int ng = 0; ng < 8; ng++) {
                uint32_t bh0, bh1, bh2, bh3, bl0, bl1, bl2, bl3;
                const uint32_t boff = (uint32_t)(ng * 16 + rB) * PJ_ROWB + (s * 16 + kB * 8) * 2;
                LDSM_X4(bh0, bh1, bh2, bh3, sb + PJ_BH + boff);
                LDSM_X4(bl0, bl1, bl2, bl3, sb + PJ_BL + boff);
                MMA16816(acc[2 * ng],     ah[s], bh0, bh1);
                MMA16816(acc[2 * ng + 1], ah[s], bh2, bh3);
                MMA16816(acc[2 * ng],     ah[s], bl0, bl1);
                MMA16816(acc[2 * ng + 1], ah[s], bl2, bl3);
                MMA16816(acc[2 * ng],     al[s], bh0, bh1);
                MMA16816(acc[2 * ng + 1], al[s], bh2, bh3);
            }
        }
    }

    // epilogue: bias add; qk -> bf16 g_qkh + g_ss, v -> fp32 g_v
    const int rl = row0 + wid * 16 + (lane >> 2);
    const int rh = rl + 8;
    if (type == 0) {
        float ss0 = 0.f, ss1 = 0.f;
#pragma unroll
        for (int nt = 0; nt < 16; nt++) {
            const int col = nt * 8 + 2 * (lane & 3);
            float2 bb = *(const float2*)&bias[col];
            float c0 = acc[nt][0] + bb.x, c1 = acc[nt][1] + bb.y;
            float c2 = acc[nt][2] + bb.x, c3 = acc[nt][3] + bb.y;
            ss0 += c0 * c0 + c1 * c1;
            ss1 += c2 * c2 + c3 * c3;
            *(uint32_t*)&g_qkh[(size_t)rl * DK + col] = bf2_to_u32(__floats2bfloat162_rn(c0, c1));
            *(uint32_t*)&g_qkh[(size_t)rh * DK + col] = bf2_to_u32(__floats2bfloat162_rn(c2, c3));
        }
        ss0 += __shfl_xor_sync(0xffffffffu, ss0, 1);
        ss0 += __shfl_xor_sync(0xffffffffu, ss0, 2);
        ss1 += __shfl_xor_sync(0xffffffffu, ss1, 1);
        ss1 += __shfl_xor_sync(0xffffffffu, ss1, 2);
        if ((lane & 3) == 0) { g_ss[rl] = ss0; g_ss[rh] = ss1; }
    } else {
#pragma unroll
        for (int nt = 0; nt < 16; nt++) {
            const int col = nt * 8 + 2 * (lane & 3);
            float2 bb = *(const float2*)&bias[col];
            float2 v0; v0.x = acc[nt][0] + bb.x; v0.y = acc[nt][1] + bb.y;
            float2 v1; v1.x = acc[nt][2] + bb.x; v1.y = acc[nt][3] + bb.y;
            *(float2*)&g_v[(size_t)rl * DV + col] = v0;
            *(float2*)&g_v[(size_t)rh * DV + col] = v1;
        }
    }
}

// ============================================================================
// attention (HMMA): BM=128 (16 rows/warp), BN=128, split-KV x2. (round-4, proven)
// ============================================================================
#define LDV 136
#define ROWB (LDV * 2)
#define AT_K0 0
#define AT_K1 34816
#define AT_VH 69632
#define AT_VL 104448
#define AT_FLAGS 139264
#define ATT_SMEM (AT_FLAGS + 64)

__global__ __launch_bounds__(256, 1)
void attn_kernel() {
    extern __shared__ char smem[];
    const uint32_t sb = smem_to_u32(smem);
    int* flags = (int*)(smem + AT_FLAGS);
    const int tid = threadIdx.x, wid = tid >> 5, lane = tid & 31;
    const int row0 = blockIdx.x * 128;
    const int h = blockIdx.y;
    const int j0base = h * 4096;

    const int rA = ((lane >> 3) & 1) * 8 + (lane & 7);
    const int kA = (lane >> 4) & 1;
    const int rB = ((lane >> 4) & 1) * 8 + (lane & 7);
    const int kB = (lane >> 3) & 1;

    const int rl = row0 + wid * 16 + (lane >> 2);
    const int rh = rl + 8;
    const float m0 = g_ss[rl], m1 = g_ss[rh];
    const float thr0 = m0 - 20.f, thr1 = m1 - 20.f;

#pragma unroll
    for (int it = 0; it < 8; it++) {
        int c = it * 256 + tid;
        int r = c >> 4, cc = (c & 15) * 8;
        cp16(sb + AT_VH + r * ROWB + cc * 2, &g_qkh[(size_t)(row0 + r) * DK + cc]);
        cp16(sb + AT_K0 + r * ROWB + cc * 2, &g_qkh[(size_t)(j0base + r) * DK + cc]);
    }
    CP_COMMIT(); CP_WAIT0();
    __syncthreads();

    uint32_t qa[8][4];
    {
        const uint32_t qrow = sb + AT_VH + (uint32_t)(wid * 16 + rA) * ROWB;
#pragma unroll
        for (int s = 0; s < 8; s++)
            LDSM_X4(qa[s][0], qa[s][1], qa[s][2], qa[s][3], qrow + (s * 16 + kA * 8) * 2);
    }
    __syncthreads();

    float oa[16][4];
#pragma unroll
    for (int nt = 0; nt < 16; nt++)
#pragma unroll
        for (int q = 0; q < 4; q++) oa[nt][q] = 0.f;
    float l0 = 0.f, l1 = 0.f;

    for (int t = 0; t < 32; t++) {
        if (t > 0) CP_WAIT0();
        __syncthreads();

        if (t + 1 < 32) {
            const uint32_t nb = sb + ((t & 1) ? AT_K0 : AT_K1);
            const int j1 = j0base + (t + 1) * 128;
#pragma unroll
            for (int it = 0; it < 8; it++) {
                int c = it * 256 + tid;
                int r = c >> 4, cc = (c & 15) * 8;
                cp16(nb + r * ROWB + cc * 2, &g_qkh[(size_t)(j1 + r) * DK + cc]);
            }
            CP_COMMIT();
        }

        const uint32_t kb = sb + ((t & 1) ? AT_K1 : AT_K0);
        float sa[16][4];
#pragma unroll
        for (int nt = 0; nt < 16; nt++)
#pragma unroll
            for (int q = 0; q < 4; q++) sa[nt][q] = 0.f;
#pragma unroll
        for (int np = 0; np < 8; np++) {
            const uint32_t krow = kb + (uint32_t)(np * 16 + rB) * ROWB;
#pragma unroll
            for (int s = 0; s < 8; s++) {
                uint32_t b0, b1, b2, b3;
                LDSM_X4(b0, b1, b2, b3, krow + (s * 16 + kB * 8) * 2);
                MMA16816(sa[2 * np],     qa[s], b0, b1);
                MMA16816(sa[2 * np + 1], qa[s], b2, b3);
            }
        }

        float mx0 = -3.0e38f, mx1 = -3.0e38f;
#pragma unroll
        for (int nt = 0; nt < 16; nt++) {
            mx0 = fmaxf(mx0, fmaxf(sa[nt][0], sa[nt][1]));
            mx1 = fmaxf(mx1, fmaxf(sa[nt][2], sa[nt][3]));
        }
        mx0 = fmaxf(mx0, __shfl_xor_sync(0xffffffffu, mx0, 1));
        mx0 = fmaxf(mx0, __shfl_xor_sync(0xffffffffu, mx0, 2));
        mx1 = fmaxf(mx1, __shfl_xor_sync(0xffffffffu, mx1, 1));
        mx1 = fmaxf(mx1, __shfl_xor_sync(0xffffffffu, mx1, 2));
        const bool act0 = mx0 >= thr0, act1 = mx1 >= thr1;
        const int wact = __any_sync(0xffffffffu, act0 || act1);
        if (lane == 0) flags[wid] = wact;
        __syncthreads();
        int cact = 0;
#pragma unroll
        for (int w = 0; w < 8; w++) cact |= flags[w];

        if (cact) {
            const int j0 = j0base + t * 128;
#pragma unroll
            for (int it = 0; it < 16; it++) {
                int idx = it * 256 + tid;
                int r = idx >> 5, cq = (idx & 31) * 4;
                float4 f = *(const float4*)&g_v[(size_t)(j0 + r) * DV + cq];
                __nv_bfloat162 h0 = __floats2bfloat162_rn(f.x, f.y);
                __nv_bfloat162 h1 = __floats2bfloat162_rn(f.z, f.w);
                __nv_bfloat162 e0 = __floats2bfloat162_rn(f.x - __bfloat162float(h0.x),
                                                          f.y - __bfloat162float(h0.y));
                __nv_bfloat162 e1 = __floats2bfloat162_rn(f.z - __bfloat162float(h1.x),
                                                          f.w - __bfloat162float(h1.y));
                uint2 uh; uh.x = bf2_to_u32(h0); uh.y = bf2_to_u32(h1);
                uint2 ul; ul.x = bf2_to_u32(e0); ul.y = bf2_to_u32(e1);
                *(uint2*)(smem + AT_VH + r * ROWB + cq * 2) = uh;
                *(uint2*)(smem + AT_VL + r * ROWB + cq * 2) = ul;
            }
            __syncthreads();

            if (wact) {
#pragma unroll
                for (int s = 0; s < 8; s++) {
                    uint32_t pa[4];
                    float e00 = act0 ? __expf(sa[2 * s][0] - m0) : 0.f;
                    float e01 = act0 ? __expf(sa[2 * s][1] - m0) : 0.f;
                    float e10 = act1 ? __expf(sa[2 * s][2] - m1) : 0.f;
                    float e11 = act1 ? __expf(sa[2 * s][3] - m1) : 0.f;
                    float f00 = act0 ? __expf(sa[2 * s + 1][0] - m0) : 0.f;
                    float f01 = act0 ? __expf(sa[2 * s + 1][1] - m0) : 0.f;
                    float f10 = act1 ? __expf(sa[2 * s + 1][2] - m1) : 0.f;
                    float f11 = act1 ? __expf(sa[2 * s + 1][3] - m1) : 0.f;
                    __nv_bfloat162 b;
                    b = __floats2bfloat162_rn(e00, e01); pa[0] = bf2_to_u32(b);
                    l0 += __bfloat162float(b.x) + __bfloat162float(b.y);
                    b = __floats2bfloat162_rn(e10, e11); pa[1] = bf2_to_u32(b);
                    l1 += __bfloat162float(b.x) + __bfloat162float(b.y);
                    b = __floats2bfloat162_rn(f00, f01); pa[2] = bf2_to_u32(b);
                    l0 += __bfloat162float(b.x) + __bfloat162float(b.y);
                    b = __floats2bfloat162_rn(f10, f11); pa[3] = bf2_to_u32(b);
                    l1 += __bfloat162float(b.x) + __bfloat162float(b.y);

                    const uint32_t vrow = (uint32_t)(s * 16 + rA) * ROWB;
#pragma unroll
                    for (int nt = 0; nt < 16; nt++) {
                        uint32_t bh0, bh1, bl0, bl1;
                        LDSM_X2_T(bh0, bh1, sb + AT_VH + vrow + nt * 16);
                        MMA16816(oa[nt], pa, bh0, bh1);
                        LDSM_X2_T(bl0, bl1, sb + AT_VL + vrow + nt * 16);
                        MMA16816(oa[nt], pa, bl0, bl1);
                    }
                }
            }
        }
    }

    l0 += __shfl_xor_sync(0xffffffffu, l0, 1);
    l0 += __shfl_xor_sync(0xffffffffu, l0, 2);
    l1 += __shfl_xor_sync(0xffffffffu, l1, 1);
    l1 += __shfl_xor_sync(0xffffffffu, l1, 2);
#pragma unroll
    for (int nt = 0; nt < 16; nt++) {
        const int col = nt * 8 + 2 * (lane & 3);
        float2 v0; v0.x = oa[nt][0]; v0.y = oa[nt][1];
        float2 v1; v1.x = oa[nt][2]; v1.y = oa[nt][3];
        *(float2*)&g_O[h][(size_t)rl * DV + col] = v0;
        *(float2*)&g_O[h][(size_t)rh * DV + col] = v1;
    }
    if ((lane & 3) == 0) {
        g_l[h][rl] = l0;
        g_l[h][rh] = l1;
    }
}

// ============================================================================
// combine: out = (O0 + O1) / (l0 + l1)
// ============================================================================
__global__ __launch_bounds__(256, 4)
void combine_kernel(float* __restrict__ out) {
    const int i4 = blockIdx.x * 256 + threadIdx.x;
    const int rowi = i4 >> 5;
    const float inv = 1.0f / (g_l[0][rowi] + g_l[1][rowi]);
    float4 a = ((const float4*)g_O[0])[i4];
    float4 b = ((const float4*)g_O[1])[i4];
    float4 o = make_float4((a.x + b.x) * inv, (a.y + b.y) * inv,
                           (a.z + b.z) * inv, (a.w + b.w) * inv);
    ((float4*)out)[i4] = o;
}

// ---------------------------------------------------------------------------
extern "C" void kernel_launch(void* const* d_in, const int* in_sizes, int n_in,
                              void* d_out, int out_size) {
    const float* x   = (const float*)d_in[0];
    const float* Wqk = (const float*)d_in[1];
    const float* bqk = (const float*)d_in[2];
    const float* Wv  = (const float*)d_in[3];
    const float* bv  = (const float*)d_in[4];
    float* out = (float*)d_out;

    cudaFuncSetAttribute(proj_hmma_kernel, cudaFuncAttributeMaxDynamicSharedMemorySize, PJ_SMEM);
    cudaFuncSetAttribute(attn_kernel, cudaFuncAttributeMaxDynamicSharedMemorySize, ATT_SMEM);

    proj_hmma_kernel<<<dim3(NTOK / 128, 2), 256, PJ_SMEM>>>(x, Wqk, bqk, Wv, bv);
    attn_kernel<<<dim3(NTOK / 128, 2), 256, ATT_SMEM>>>();
    combine_kernel<<<1024, 256>>>(out);
}

// round 6
// speedup vs baseline: 7.1129x; 1.0004x over previous
#include <cuda_runtime.h>
#include <cuda_bf16.h>
#include <stdint.h>

#define NTOK 8192
#define DIM  1024
#define DK   128
#define DV   128

// ---------------- device globals (allocation-free scratch) ----------------
__device__ float g_v[NTOK * DV];
__device__ __align__(256) __nv_bfloat16 g_qkh[NTOK * DK];   // qk bf16 row-major
__device__ __align__(256) float g_ss[NTOK];                 // ||qk_i||^2 fp32
__device__ __align__(256) float g_O[2][NTOK * DV];          // split-KV numerators
__device__ __align__(256) float g_l[2][NTOK];               // split-KV denominators

// ---------------- helpers ----------------
__device__ __forceinline__ uint32_t smem_to_u32(const void* p) {
    uint32_t a;
    asm("{ .reg .u64 t; cvta.to.shared.u64 t, %1; cvt.u32.u64 %0, t; }" : "=r"(a) : "l"(p));
    return a;
}
__device__ __forceinline__ void cp16(uint32_t dst, const void* src) {
    asm volatile("cp.async.cg.shared.global [%0], [%1], 16;" :: "r"(dst), "l"(src) : "memory");
}
#define CP_COMMIT() asm volatile("cp.async.commit_group;" ::: "memory")
#define CP_WAIT0()  asm volatile("cp.async.wait_group 0;" ::: "memory")

__device__ __forceinline__ uint32_t bf2_to_u32(__nv_bfloat162 v) {
    uint32_t u; *(__nv_bfloat162*)&u = v; return u;
}

#define LDSM_X4(r0, r1, r2, r3, a) \
    asm volatile("ldmatrix.sync.aligned.m8n8.x4.shared.b16 {%0,%1,%2,%3}, [%4];" \
                 : "=r"(r0), "=r"(r1), "=r"(r2), "=r"(r3) : "r"(a))
#define LDSM_X2_T(r0, r1, a) \
    asm volatile("ldmatrix.sync.aligned.m8n8.x2.trans.shared.b16 {%0,%1}, [%2];" \
                 : "=r"(r0), "=r"(r1) : "r"(a))
// D(f32 4) += A(bf16 16x16) * B(bf16 16x8 col)
#define MMA16816(d, a, b0, b1) \
    asm volatile("mma.sync.aligned.m16n8k16.row.col.f32.bf16.bf16.f32 " \
                 "{%0,%1,%2,%3}, {%4,%5,%6,%7}, {%8,%9}, {%0,%1,%2,%3};" \
                 : "+f"((d)[0]), "+f"((d)[1]), "+f"((d)[2]), "+f"((d)[3]) \
                 : "r"((a)[0]), "r"((a)[1]), "r"((a)[2]), "r"((a)[3]), "r"(b0), "r"(b1))

// ============================================================================
// proj (HMMA, bf16 hi/lo 3-product split): out[n,c] = x[n]·W[c] + b[c]
// (round-5, proven — unchanged)
// ============================================================================
#define PJ_ROWB 144
#define PJ_AH 0
#define PJ_AL 18432
#define PJ_BH 36864
#define PJ_BL 55296
#define PJ_SA 73728
#define PJ_SB 106496
#define PJ_SMEM 139264

__global__ __launch_bounds__(256, 1)
void proj_hmma_kernel(const float* __restrict__ x,
                      const float* __restrict__ Wqk, const float* __restrict__ bqk,
                      const float* __restrict__ Wv,  const float* __restrict__ bv) {
    extern __shared__ char smem[];
    const uint32_t sb = smem_to_u32(smem);
    const int tid = threadIdx.x, wid = tid >> 5, lane = tid & 31;
    const int row0 = blockIdx.x * 128;
    const int type = blockIdx.y;
    const float* W = type ? Wv : Wqk;
    const float* bias = type ? bv : bqk;

    const int rA = ((lane >> 3) & 1) * 8 + (lane & 7);
    const int kA = (lane >> 4) & 1;
    const int rB = ((lane >> 4) & 1) * 8 + (lane & 7);
    const int kB = (lane >> 3) & 1;

    float acc[16][4];
#pragma unroll
    for (int nt = 0; nt < 16; nt++)
#pragma unroll
        for (int q = 0; q < 4; q++) acc[nt][q] = 0.f;

#pragma unroll
    for (int it = 0; it < 8; it++) {
        int idx = it * 256 + tid;
        int r = idx >> 4, kq = (idx & 15) * 4;
        cp16(sb + PJ_SA + r * 256 + kq * 4, &x[(size_t)(row0 + r) * DIM + kq]);
        cp16(sb + PJ_SB + r * 256 + kq * 4, &W[(size_t)r * DIM + kq]);
    }
    CP_COMMIT();

    for (int c = 0; c < 16; c++) {
        CP_WAIT0();
        __syncthreads();

#pragma unroll
        for (int it = 0; it < 8; it++) {
            int idx = it * 256 + tid;
            int r = idx >> 4, kq = (idx & 15) * 4;
            float4 fa = *(const float4*)(smem + PJ_SA + r * 256 + kq * 4);
            float4 fb = *(const float4*)(smem + PJ_SB + r * 256 + kq * 4);
            __nv_bfloat162 ah0 = __floats2bfloat162_rn(fa.x, fa.y);
            __nv_bfloat162 ah1 = __floats2bfloat162_rn(fa.z, fa.w);
            __nv_bfloat162 al0 = __floats2bfloat162_rn(fa.x - __bfloat162float(ah0.x),
                                                       fa.y - __bfloat162float(ah0.y));
            __nv_bfloat162 al1 = __floats2bfloat162_rn(fa.z - __bfloat162float(ah1.x),
                                                       fa.w - __bfloat162float(ah1.y));
            __nv_bfloat162 bh0 = __floats2bfloat162_rn(fb.x, fb.y);
            __nv_bfloat162 bh1 = __floats2bfloat162_rn(fb.z, fb.w);
            __nv_bfloat162 bl0 = __floats2bfloat162_rn(fb.x - __bfloat162float(bh0.x),
                                                       fb.y - __bfloat162float(bh0.y));
            __nv_bfloat162 bl1 = __floats2bfloat162_rn(fb.z - __bfloat162float(bh1.x),
                                                       fb.w - __bfloat162float(bh1.y));
            uint2 u;
            u.x = bf2_to_u32(ah0); u.y = bf2_to_u32(ah1);
            *(uint2*)(smem + PJ_AH + r * PJ_ROWB + kq * 2) = u;
            u.x = bf2_to_u32(al0); u.y = bf2_to_u32(al1);
            *(uint2*)(smem + PJ_AL + r * PJ_ROWB + kq * 2) = u;
            u.x = bf2_to_u32(bh0); u.y = bf2_to_u32(bh1);
            *(uint2*)(smem + PJ_BH + r * PJ_ROWB + kq * 2) = u;
            u.x = bf2_to_u32(bl0); u.y = bf2_to_u32(bl1);
            *(uint2*)(smem + PJ_BL + r * PJ_ROWB + kq * 2) = u;
        }
        __syncthreads();

        if (c + 1 < 16) {
            const int kk = (c + 1) * 64;
#pragma unroll
            for (int it = 0; it < 8; it++) {
                int idx = it * 256 + tid;
                int r = idx >> 4, kq = (idx & 15) * 4;
                cp16(sb + PJ_SA + r * 256 + kq * 4, &x[(size_t)(row0 + r) * DIM + kk + kq]);
                cp16(sb + PJ_SB + r * 256 + kq * 4, &W[(size_t)r * DIM + kk + kq]);
            }
            CP_COMMIT();
        }

        uint32_t ah[4][4], al[4][4];
        const uint32_t arh = sb + PJ_AH + (uint32_t)(wid * 16 + rA) * PJ_ROWB;
        const uint32_t arl = sb + PJ_AL + (uint32_t)(wid * 16 + rA) * PJ_ROWB;
#pragma unroll
        for (int s = 0; s < 4; s++) {
            LDSM_X4(ah[s][0], ah[s][1], ah[s][2], ah[s][3], arh + (s * 16 + kA * 8) * 2);
            LDSM_X4(al[s][0], al[s][1], al[s][2], al[s][3], arl + (s * 16 + kA * 8) * 2);
        }

#pragma unroll
        for (int s = 0; s < 4; s++) {
#pragma unroll
            for (int ng = 0; ng < 8; ng++) {
                uint32_t bh0, bh1, bh2, bh3, bl0, bl1, bl2, bl3;
                const uint32_t boff = (uint32_t)(ng * 16 + rB) * PJ_ROWB + (s * 16 + kB * 8) * 2;
                LDSM_X4(bh0, bh1, bh2, bh3, sb + PJ_BH + boff);
                LDSM_X4(bl0, bl1, bl2, bl3, sb + PJ_BL + boff);
                MMA16816(acc[2 * ng],     ah[s], bh0, bh1);
                MMA16816(acc[2 * ng + 1], ah[s], bh2, bh3);
                MMA16816(acc[2 * ng],     ah[s], bl0, bl1);
                MMA16816(acc[2 * ng + 1], ah[s], bl2, bl3);
                MMA16816(acc[2 * ng],     al[s], bh0, bh1);
                MMA16816(acc[2 * ng + 1], al[s], bh2, bh3);
            }
        }
    }

    const int rl = row0 + wid * 16 + (lane >> 2);
    const int rh = rl + 8;
    if (type == 0) {
        float ss0 = 0.f, ss1 = 0.f;
#pragma unroll
        for (int nt = 0; nt < 16; nt++) {
            const int col = nt * 8 + 2 * (lane & 3);
            float2 bb = *(const float2*)&bias[col];
            float c0 = acc[nt][0] + bb.x, c1 = acc[nt][1] + bb.y;
            float c2 = acc[nt][2] + bb.x, c3 = acc[nt][3] + bb.y;
            ss0 += c0 * c0 + c1 * c1;
            ss1 += c2 * c2 + c3 * c3;
            *(uint32_t*)&g_qkh[(size_t)rl * DK + col] = bf2_to_u32(__floats2bfloat162_rn(c0, c1));
            *(uint32_t*)&g_qkh[(size_t)rh * DK + col] = bf2_to_u32(__floats2bfloat162_rn(c2, c3));
        }
        ss0 += __shfl_xor_sync(0xffffffffu, ss0, 1);
        ss0 += __shfl_xor_sync(0xffffffffu, ss0, 2);
        ss1 += __shfl_xor_sync(0xffffffffu, ss1, 1);
        ss1 += __shfl_xor_sync(0xffffffffu, ss1, 2);
        if ((lane & 3) == 0) { g_ss[rl] = ss0; g_ss[rh] = ss1; }
    } else {
#pragma unroll
        for (int nt = 0; nt < 16; nt++) {
            const int col = nt * 8 + 2 * (lane & 3);
            float2 bb = *(const float2*)&bias[col];
            float2 v0; v0.x = acc[nt][0] + bb.x; v0.y = acc[nt][1] + bb.y;
            float2 v1; v1.x = acc[nt][2] + bb.x; v1.y = acc[nt][3] + bb.y;
            *(float2*)&g_v[(size_t)rl * DV + col] = v0;
            *(float2*)&g_v[(size_t)rh * DV + col] = v1;
        }
    }
}

// ============================================================================
// attention (HMMA): BM=128 (16 rows/warp), BN=128, split-KV x2.
// Round-6 change: S loop reordered s-outer/np-inner -> 16-accumulator ILP;
// PV hi/lo split into two 16-deep passes.
// ============================================================================
#define LDV 136
#define ROWB (LDV * 2)
#define AT_K0 0
#define AT_K1 34816
#define AT_VH 69632
#define AT_VL 104448
#define AT_FLAGS 139264
#define ATT_SMEM (AT_FLAGS + 64)

__global__ __launch_bounds__(256, 1)
void attn_kernel() {
    extern __shared__ char smem[];
    const uint32_t sb = smem_to_u32(smem);
    int* flags = (int*)(smem + AT_FLAGS);
    const int tid = threadIdx.x, wid = tid >> 5, lane = tid & 31;
    const int row0 = blockIdx.x * 128;
    const int h = blockIdx.y;
    const int j0base = h * 4096;

    const int rA = ((lane >> 3) & 1) * 8 + (lane & 7);
    const int kA = (lane >> 4) & 1;
    const int rB = ((lane >> 4) & 1) * 8 + (lane & 7);
    const int kB = (lane >> 3) & 1;

    const int rl = row0 + wid * 16 + (lane >> 2);
    const int rh = rl + 8;
    const float m0 = g_ss[rl], m1 = g_ss[rh];
    const float thr0 = m0 - 20.f, thr1 = m1 - 20.f;

#pragma unroll
    for (int it = 0; it < 8; it++) {
        int c = it * 256 + tid;
        int r = c >> 4, cc = (c & 15) * 8;
        cp16(sb + AT_VH + r * ROWB + cc * 2, &g_qkh[(size_t)(row0 + r) * DK + cc]);
        cp16(sb + AT_K0 + r * ROWB + cc * 2, &g_qkh[(size_t)(j0base + r) * DK + cc]);
    }
    CP_COMMIT(); CP_WAIT0();
    __syncthreads();

    uint32_t qa[8][4];
    {
        const uint32_t qrow = sb + AT_VH + (uint32_t)(wid * 16 + rA) * ROWB;
#pragma unroll
        for (int s = 0; s < 8; s++)
            LDSM_X4(qa[s][0], qa[s][1], qa[s][2], qa[s][3], qrow + (s * 16 + kA * 8) * 2);
    }
    __syncthreads();

    float oa[16][4];
#pragma unroll
    for (int nt = 0; nt < 16; nt++)
#pragma unroll
        for (int q = 0; q < 4; q++) oa[nt][q] = 0.f;
    float l0 = 0.f, l1 = 0.f;

    for (int t = 0; t < 32; t++) {
        if (t > 0) CP_WAIT0();
        __syncthreads();

        if (t + 1 < 32) {
            const uint32_t nb = sb + ((t & 1) ? AT_K0 : AT_K1);
            const int j1 = j0base + (t + 1) * 128;
#pragma unroll
            for (int it = 0; it < 8; it++) {
                int c = it * 256 + tid;
                int r = c >> 4, cc = (c & 15) * 8;
                cp16(nb + r * ROWB + cc * 2, &g_qkh[(size_t)(j1 + r) * DK + cc]);
            }
            CP_COMMIT();
        }

        // S = Q K^T: s OUTER, np INNER -> 16 accumulators between reuse
        const uint32_t kb = sb + ((t & 1) ? AT_K1 : AT_K0);
        float sa[16][4];
#pragma unroll
        for (int nt = 0; nt < 16; nt++)
#pragma unroll
            for (int q = 0; q < 4; q++) sa[nt][q] = 0.f;
#pragma unroll
        for (int s = 0; s < 8; s++) {
            const uint32_t kcol = kb + (uint32_t)((s * 16 + kB * 8) * 2);
#pragma unroll
            for (int np = 0; np < 8; np++) {
                uint32_t b0, b1, b2, b3;
                LDSM_X4(b0, b1, b2, b3, kcol + (uint32_t)(np * 16 + rB) * ROWB);
                MMA16816(sa[2 * np],     qa[s], b0, b1);
                MMA16816(sa[2 * np + 1], qa[s], b2, b3);
            }
        }

        float mx0 = -3.0e38f, mx1 = -3.0e38f;
#pragma unroll
        for (int nt = 0; nt < 16; nt++) {
            mx0 = fmaxf(mx0, fmaxf(sa[nt][0], sa[nt][1]));
            mx1 = fmaxf(mx1, fmaxf(sa[nt][2], sa[nt][3]));
        }
        mx0 = fmaxf(mx0, __shfl_xor_sync(0xffffffffu, mx0, 1));
        mx0 = fmaxf(mx0, __shfl_xor_sync(0xffffffffu, mx0, 2));
        mx1 = fmaxf(mx1, __shfl_xor_sync(0xffffffffu, mx1, 1));
        mx1 = fmaxf(mx1, __shfl_xor_sync(0xffffffffu, mx1, 2));
        const bool act0 = mx0 >= thr0, act1 = mx1 >= thr1;
        const int wact = __any_sync(0xffffffffu, act0 || act1);
        if (lane == 0) flags[wid] = wact;
        __syncthreads();
        int cact = 0;
#pragma unroll
        for (int w = 0; w < 8; w++) cact |= flags[w];

        if (cact) {
            const int j0 = j0base + t * 128;
#pragma unroll
            for (int it = 0; it < 16; it++) {
                int idx = it * 256 + tid;
                int r = idx >> 5, cq = (idx & 31) * 4;
                float4 f = *(const float4*)&g_v[(size_t)(j0 + r) * DV + cq];
                __nv_bfloat162 h0 = __floats2bfloat162_rn(f.x, f.y);
                __nv_bfloat162 h1 = __floats2bfloat162_rn(f.z, f.w);
                __nv_bfloat162 e0 = __floats2bfloat162_rn(f.x - __bfloat162float(h0.x),
                                                          f.y - __bfloat162float(h0.y));
                __nv_bfloat162 e1 = __floats2bfloat162_rn(f.z - __bfloat162float(h1.x),
                                                          f.w - __bfloat162float(h1.y));
                uint2 uh; uh.x = bf2_to_u32(h0); uh.y = bf2_to_u32(h1);
                uint2 ul; ul.x = bf2_to_u32(e0); ul.y = bf2_to_u32(e1);
                *(uint2*)(smem + AT_VH + r * ROWB + cq * 2) = uh;
                *(uint2*)(smem + AT_VL + r * ROWB + cq * 2) = ul;
            }
            __syncthreads();

            if (wact) {
#pragma unroll
                for (int s = 0; s < 8; s++) {
                    uint32_t pa[4];
                    float e00 = act0 ? __expf(sa[2 * s][0] - m0) : 0.f;
                    float e01 = act0 ? __expf(sa[2 * s][1] - m0) : 0.f;
                    float e10 = act1 ? __expf(sa[2 * s][2] - m1) : 0.f;
                    float e11 = act1 ? __expf(sa[2 * s][3] - m1) : 0.f;
                    float f00 = act0 ? __expf(sa[2 * s + 1][0] - m0) : 0.f;
                    float f01 = act0 ? __expf(sa[2 * s + 1][1] - m0) : 0.f;
                    float f10 = act1 ? __expf(sa[2 * s + 1][2] - m1) : 0.f;
                    float f11 = act1 ? __expf(sa[2 * s + 1][3] - m1) : 0.f;
                    __nv_bfloat162 b;
                    b = __floats2bfloat162_rn(e00, e01); pa[0] = bf2_to_u32(b);
                    l0 += __bfloat162float(b.x) + __bfloat162float(b.y);
                    b = __floats2bfloat162_rn(e10, e11); pa[1] = bf2_to_u32(b);
                    l1 += __bfloat162float(b.x) + __bfloat162float(b.y);
                    b = __floats2bfloat162_rn(f00, f01); pa[2] = bf2_to_u32(b);
                    l0 += __bfloat162float(b.x) + __bfloat162float(b.y);
                    b = __floats2bfloat162_rn(f10, f11); pa[3] = bf2_to_u32(b);
                    l1 += __bfloat162float(b.x) + __bfloat162float(b.y);

                    const uint32_t vrow = (uint32_t)(s * 16 + rA) * ROWB;
                    // hi pass: 16-deep accumulator cycle
#pragma unroll
                    for (int nt = 0; nt < 16; nt++) {
                        uint32_t bh0, bh1;
                        LDSM_X2_T(bh0, bh1, sb + AT_VH + vrow + nt * 16);
                        MMA16816(oa[nt], pa, bh0, bh1);
                    }
                    // lo pass
#pragma unroll
                    for (int nt = 0; nt < 16; nt++) {
                        uint32_t bl0, bl1;
                        LDSM_X2_T(bl0, bl1, sb + AT_VL + vrow + nt * 16);
                        MMA16816(oa[nt], pa, bl0, bl1);
                    }
                }
            }
        }
    }

    l0 += __shfl_xor_sync(0xffffffffu, l0, 1);
    l0 += __shfl_xor_sync(0xffffffffu, l0, 2);
    l1 += __shfl_xor_sync(0xffffffffu, l1, 1);
    l1 += __shfl_xor_sync(0xffffffffu, l1, 2);
#pragma unroll
    for (int nt = 0; nt < 16; nt++) {
        const int col = nt * 8 + 2 * (lane & 3);
        float2 v0; v0.x = oa[nt][0]; v0.y = oa[nt][1];
        float2 v1; v1.x = oa[nt][2]; v1.y = oa[nt][3];
        *(float2*)&g_O[h][(size_t)rl * DV + col] = v0;
        *(float2*)&g_O[h][(size_t)rh * DV + col] = v1;
    }
    if ((lane & 3) == 0) {
        g_l[h][rl] = l0;
        g_l[h][rh] = l1;
    }
}

// ============================================================================
// combine: out = (O0 + O1) / (l0 + l1)
// ============================================================================
__global__ __launch_bounds__(256, 4)
void combine_kernel(float* __restrict__ out) {
    const int i4 = blockIdx.x * 256 + threadIdx.x;
    const int rowi = i4 >> 5;
    const float inv = 1.0f / (g_l[0][rowi] + g_l[1][rowi]);
    float4 a = ((const float4*)g_O[0])[i4];
    float4 b = ((const float4*)g_O[1])[i4];
    float4 o = make_float4((a.x + b.x) * inv, (a.y + b.y) * inv,
                           (a.z + b.z) * inv, (a.w + b.w) * inv);
    ((float4*)out)[i4] = o;
}

// ---------------------------------------------------------------------------
extern "C" void kernel_launch(void* const* d_in, const int* in_sizes, int n_in,
                              void* d_out, int out_size) {
    const float* x   = (const float*)d_in[0];
    const float* Wqk = (const float*)d_in[1];
    const float* bqk = (const float*)d_in[2];
    const float* Wv  = (const float*)d_in[3];
    const float* bv  = (const float*)d_in[4];
    float* out = (float*)d_out;

    cudaFuncSetAttribute(proj_hmma_kernel, cudaFuncAttributeMaxDynamicSharedMemorySize, PJ_SMEM);
    cudaFuncSetAttribute(attn_kernel, cudaFuncAttributeMaxDynamicSharedMemorySize, ATT_SMEM);

    proj_hmma_kernel<<<dim3(NTOK / 128, 2), 256, PJ_SMEM>>>(x, Wqk, bqk, Wv, bv);
    attn_kernel<<<dim3(NTOK / 128, 2), 256, ATT_SMEM>>>();
    combine_kernel<<<1024, 256>>>(out);
}